// round 12
// baseline (speedup 1.0000x reference)
#include <cuda_runtime.h>
#include <cuda_fp16.h>
#include <cstdint>
#include <cstddef>

// Problem dims
#define B_ 2
#define M_ 384
#define N_ 96
#define D_ 512
#define J_ 640
#define C_ 1024
#define MN_ (M_*N_)        // 36864
#define RTOT_ (B_*MN_)     // 73728

// Join tiling: BM=64 x BN=256 x BK=64, 256 threads, 8 warps (2m x 4n), warp 32x64
#define BM 64
#define BN 256
#define BK 64
#define NKT (J_/BK)        // 10
#define THREADS 256

// fp16 row-major tiles, 144B row stride
#define ROWB 144
#define HS_B (BM*ROWB)     // 9216
#define WS_B (BN*ROWB)     // 36864

#define SM_AOFF  0
#define SM_TOFF  256
#define SM_HS    1024
#define SM_WS    (SM_HS + 2*HS_B)      // 19456
#define SMEM_TOTAL (SM_WS + 2*WS_B)    // 93184

// prep grid split (256-thread blocks)
#define NB_WPACK (((C_/32)*(J_/32))/2)   // 320  (2 transpose tiles per block)
#define NB_ENC   ((B_*M_/16)*(J_/128))   // 48*5 = 240
#define NB_DEC   ((B_*N_/16)*(J_/128))   // 12*5 = 60
#define NB_PREP  (NB_WPACK + NB_ENC + NB_DEC)  // 620

// Scratch (device globals)
__device__ __half g_ah[B_*M_*J_];
__device__ __half g_th[B_*N_*J_];
__device__ __half g_wh[(size_t)C_*J_];   // w_join transposed [col][j], fp16

// ---------------------------------------------------------------------------
// helpers
// ---------------------------------------------------------------------------
__device__ __forceinline__ uint32_t smem_u32(const void* p) {
    uint32_t a;
    asm("{ .reg .u64 t; cvta.to.shared.u64 t, %1; cvt.u32.u64 %0, t; }"
        : "=r"(a) : "l"(p));
    return a;
}
__device__ __forceinline__ float fast_tanh(float x) {
    float r;
    asm("tanh.approx.f32 %0, %1;" : "=f"(r) : "f"(x));
    return r;
}
__device__ __forceinline__ unsigned pack_h2(float lo, float hi) {
    unsigned r;
    asm("cvt.rn.f16x2.f32 %0, %2, %1;" : "=r"(r) : "f"(lo), "f"(hi));
    return r;
}
__device__ __forceinline__ void mma_f16(float d[4],
                                        unsigned a0, unsigned a1, unsigned a2, unsigned a3,
                                        unsigned b0, unsigned b1) {
    asm volatile(
        "mma.sync.aligned.m16n8k16.row.col.f32.f16.f16.f32 "
        "{%0,%1,%2,%3}, {%4,%5,%6,%7}, {%8,%9}, {%0,%1,%2,%3};"
        : "+f"(d[0]), "+f"(d[1]), "+f"(d[2]), "+f"(d[3])
        : "r"(a0), "r"(a1), "r"(a2), "r"(a3), "r"(b0), "r"(b1));
}
__device__ __forceinline__ void ldm_x4(unsigned r[4], uint32_t addr) {
    asm volatile("ldmatrix.sync.aligned.m8n8.x4.shared.b16 {%0,%1,%2,%3}, [%4];"
        : "=r"(r[0]), "=r"(r[1]), "=r"(r[2]), "=r"(r[3]) : "r"(addr));
}
__device__ __forceinline__ void cp_async16(uint32_t dst, const void* src) {
    asm volatile("cp.async.ca.shared.global [%0], [%1], 16;" :: "r"(dst), "l"(src));
}
#define CP_COMMIT() asm volatile("cp.async.commit_group;" ::: "memory")
#define CP_WAIT0()  asm volatile("cp.async.wait_group 0;" ::: "memory")

__device__ __forceinline__ uint4 h_combine(uint4 a, uint4 t) {
    uint4 q;
    unsigned* av = (unsigned*)&a;
    unsigned* tv = (unsigned*)&t;
    unsigned* qv = (unsigned*)&q;
#pragma unroll
    for (int i = 0; i < 4; ++i) {
        float2 af = __half22float2(*(__half2*)&av[i]);
        float2 tf = __half22float2(*(__half2*)&tv[i]);
        qv[i] = pack_h2(fast_tanh(af.x + tf.x), fast_tanh(af.y + tf.y));
    }
    return q;
}

// ---------------------------------------------------------------------------
// Fused prep kernel, 256 threads/block:
//   [0, 320)    w_join transpose: 2 x (32x32) tiles per block
//   [320, 560)  enc projection  (16 rows x 128 cols)
//   [560, 620)  dec projection  (16 rows x 128 cols)
// ---------------------------------------------------------------------------
__device__ __forceinline__ void proj_part(
    const float* __restrict__ x, const float* __restrict__ w,
    const float* __restrict__ bias, __half* __restrict__ outp,
    int rb, int cb, int tid)
{
    __shared__ float xs[16][D_];
    const int r0 = rb * 16;
    const int j  = cb * 128 + (tid & 31) * 4;
    const int rw = tid >> 5;                  // 0..7; rows rw, rw+8

    for (int i = tid; i < 16 * D_ / 4; i += 256)
        ((float4*)xs)[i] = ((const float4*)x)[(size_t)r0 * (D_ / 4) + i];
    __syncthreads();

    float4 a0 = make_float4(0.f, 0.f, 0.f, 0.f);
    float4 a1 = make_float4(0.f, 0.f, 0.f, 0.f);
#pragma unroll 8
    for (int k = 0; k < D_; ++k) {
        float4 wv = *(const float4*)&w[(size_t)k * J_ + j];
        float x0 = xs[rw][k], x1 = xs[rw + 8][k];
        a0.x += x0 * wv.x; a0.y += x0 * wv.y; a0.z += x0 * wv.z; a0.w += x0 * wv.w;
        a1.x += x1 * wv.x; a1.y += x1 * wv.y; a1.z += x1 * wv.z; a1.w += x1 * wv.w;
    }
    float4 bb = *(const float4*)&bias[j];
    uint2 o0, o1;
    o0.x = pack_h2(a0.x + bb.x, a0.y + bb.y);
    o0.y = pack_h2(a0.z + bb.z, a0.w + bb.w);
    o1.x = pack_h2(a1.x + bb.x, a1.y + bb.y);
    o1.y = pack_h2(a1.z + bb.z, a1.w + bb.w);
    *(uint2*)&outp[(size_t)(r0 + rw) * J_ + j]     = o0;
    *(uint2*)&outp[(size_t)(r0 + rw + 8) * J_ + j] = o1;
}

__global__ __launch_bounds__(256) void prep_kernel(
    const float* __restrict__ enc, const float* __restrict__ dec,
    const float* __restrict__ w_audio, const float* __restrict__ b_audio,
    const float* __restrict__ w_text,  const float* __restrict__ b_text,
    const float* __restrict__ wj)
{
    const int bid = blockIdx.x;
    const int tid = threadIdx.x;

    if (bid < NB_WPACK) {
        // two 32x32 transpose tiles; tile index = bid*2 + (tid>>7)
        __shared__ float t[2][32][33];
        const int tt  = tid >> 7;            // 0/1
        const int lt  = tid & 127;
        const int tile = bid * 2 + tt;
        const int c0 = (tile & 31) * 32;
        const int j0 = (tile >> 5) * 32;
        const int tx = lt & 31, ty = lt >> 5;   // ty 0..3
#pragma unroll
        for (int i = 0; i < 8; ++i)
            t[tt][ty + i * 4][tx] = wj[(size_t)(j0 + ty + i * 4) * C_ + c0 + tx];
        __syncthreads();
#pragma unroll
        for (int i = 0; i < 8; ++i)
            g_wh[(size_t)(c0 + ty + i * 4) * J_ + j0 + tx] =
                __float2half(t[tt][tx][ty + i * 4]);
    } else if (bid < NB_WPACK + NB_ENC) {
        const int pb = bid - NB_WPACK;
        proj_part(enc, w_audio, b_audio, g_ah, pb / 5, pb % 5, tid);
    } else {
        const int pb = bid - NB_WPACK - NB_ENC;
        proj_part(dec, w_text, b_text, g_th, pb / 5, pb % 5, tid);
    }
}

// ---------------------------------------------------------------------------
// Fused join GEMM, fp16 mma + ldmatrix, BK=64, 2 CTAs/SM, phase-staggered.
// ---------------------------------------------------------------------------
__global__ __launch_bounds__(THREADS, 2) void join_kernel(
    const float* __restrict__ bj, float* __restrict__ out)
{
    extern __shared__ char sm[];
    const uint32_t sb = smem_u32(sm);
    const int tid  = threadIdx.x;
    const int wid  = tid >> 5;
    const int lane = tid & 31;
    const int col0 = blockIdx.x * BN;
    const int row0 = blockIdx.y * BM;
    // K-loop rotation: de-phase co-resident CTAs (fp32 acc -> order invariant)
    const int off = ((blockIdx.x ^ blockIdx.y) & 1) * (NKT / 2);

    int* aoffS = (int*)(sm + SM_AOFF);
    int* toffS = (int*)(sm + SM_TOFF);
    if (tid < BM) {
        int gr  = row0 + tid;
        int b   = gr / MN_;
        int rem = gr - b * MN_;
        int m   = rem / N_;
        int n   = rem - m * N_;
        aoffS[tid] = (b * M_ + m) * J_;
        toffS[tid] = (b * N_ + n) * J_;
    }
    __syncthreads();

    const int hrow = tid >> 2;              // 0..63
    const int kq   = tid & 3;
    const int aoff = aoffS[hrow] + kq * 16;
    const int toff = toffS[hrow] + kq * 16;

    const int wm = wid & 1;
    const int wn = wid >> 1;
    const int g  = lane >> 2;
    const int c  = lane & 3;

    const int l7 = lane & 7;
    const int lm = lane >> 3;
    const uint32_t a_loc = (uint32_t)((wm * 32 + (lm & 1) * 8 + l7) * ROWB + (lm >> 1) * 16);
    const uint32_t b_loc = (uint32_t)((wn * 64 + (lm >> 1) * 8 + l7) * ROWB + (lm & 1) * 16);

    float acc[2][8][4];
#pragma unroll
    for (int mi = 0; mi < 2; ++mi)
#pragma unroll
        for (int ni = 0; ni < 8; ++ni)
#pragma unroll
            for (int q = 0; q < 4; ++q) acc[mi][ni][q] = 0.f;

    // ---------------- prologue: first tile (kt = off) ----------------
    {
        const int k0 = off * BK;
        uint4 va0 = *(const uint4*)(g_ah + aoff + k0);
        uint4 va1 = *(const uint4*)(g_ah + aoff + k0 + 8);
        uint4 vt0 = *(const uint4*)(g_th + toff + k0);
        uint4 vt1 = *(const uint4*)(g_th + toff + k0 + 8);

        uint32_t wbase = sb + SM_WS;
        const size_t ksrc = (size_t)k0 * 2;
#pragma unroll
        for (int p = 0; p < 8; ++p) {
            int cid = tid + p * THREADS;
            int cc  = cid >> 3;
            int kk  = cid & 7;
            cp_async16(wbase + cc * ROWB + kk * 16,
                       (const char*)g_wh + (size_t)(col0 + cc) * J_ * 2 + ksrc + kk * 16);
        }
        CP_COMMIT();

        char* hd = sm + SM_HS + hrow * ROWB + kq * 32;
        *(uint4*)(hd)      = h_combine(va0, vt0);
        *(uint4*)(hd + 16) = h_combine(va1, vt1);

        CP_WAIT0();
        __syncthreads();
    }

    // ---------------- main loop (rotated order) ----------------
    for (int s = 0; s < NKT; ++s) {
        const int buf = s & 1;
        const int nb  = buf ^ 1;
        int ktn = s + 1 + off;  if (ktn >= NKT) ktn -= NKT;  // next tile index
        const uint32_t ha = sb + SM_HS + buf * HS_B + a_loc;
        const uint32_t hb = sb + SM_WS + buf * WS_B + b_loc;
        const bool more = (s < NKT - 1);

        uint4 va0, va1, vt0, vt1;
        if (more) {
            const int k0n = ktn * BK;
            va0 = *(const uint4*)(g_ah + aoff + k0n);
            va1 = *(const uint4*)(g_ah + aoff + k0n + 8);
            vt0 = *(const uint4*)(g_th + toff + k0n);
            vt1 = *(const uint4*)(g_th + toff + k0n + 8);

            uint32_t wbase = sb + SM_WS + nb * WS_B;
            const size_t ksrc = (size_t)k0n * 2;
#pragma unroll
            for (int p = 0; p < 8; ++p) {
                int cid = tid + p * THREADS;
                int cc  = cid >> 3;
                int kk  = cid & 7;
                cp_async16(wbase + cc * ROWB + kk * 16,
                           (const char*)g_wh + (size_t)(col0 + cc) * J_ * 2 + ksrc + kk * 16);
            }
            CP_COMMIT();
        }

        // compute ks 0..1
#pragma unroll
        for (int ks = 0; ks < 2; ++ks) {
            unsigned af[2][4];
            ldm_x4(af[0], ha + ks * 32);
            ldm_x4(af[1], ha + 16 * ROWB + ks * 32);
            unsigned bf[4][4];
#pragma unroll
            for (int p = 0; p < 4; ++p)
                ldm_x4(bf[p], hb + p * (16 * ROWB) + ks * 32);
#pragma unroll
            for (int p = 0; p < 4; ++p)
#pragma unroll
                for (int mi = 0; mi < 2; ++mi) {
                    mma_f16(acc[mi][2 * p],
                            af[mi][0], af[mi][1], af[mi][2], af[mi][3],
                            bf[p][0], bf[p][1]);
                    mma_f16(acc[mi][2 * p + 1],
                            af[mi][0], af[mi][1], af[mi][2], af[mi][3],
                            bf[p][2], bf[p][3]);
                }
        }

        // interleave next-tile h fill here (tensor pipe keeps draining MMAs)
        if (more) {
            char* hd = sm + SM_HS + nb * HS_B + hrow * ROWB + kq * 32;
            *(uint4*)(hd)      = h_combine(va0, vt0);
            *(uint4*)(hd + 16) = h_combine(va1, vt1);
        }

        // compute ks 2..3
#pragma unroll
        for (int ks = 2; ks < 4; ++ks) {
            unsigned af[2][4];
            ldm_x4(af[0], ha + ks * 32);
            ldm_x4(af[1], ha + 16 * ROWB + ks * 32);
            unsigned bf[4][4];
#pragma unroll
            for (int p = 0; p < 4; ++p)
                ldm_x4(bf[p], hb + p * (16 * ROWB) + ks * 32);
#pragma unroll
            for (int p = 0; p < 4; ++p)
#pragma unroll
                for (int mi = 0; mi < 2; ++mi) {
                    mma_f16(acc[mi][2 * p],
                            af[mi][0], af[mi][1], af[mi][2], af[mi][3],
                            bf[p][0], bf[p][1]);
                    mma_f16(acc[mi][2 * p + 1],
                            af[mi][0], af[mi][1], af[mi][2], af[mi][3],
                            bf[p][2], bf[p][3]);
                }
        }

        if (more) CP_WAIT0();
        __syncthreads();
    }

    // ---------------- epilogue: + b_join, fp32 stores ----------------
#pragma unroll
    for (int ni = 0; ni < 8; ++ni) {
        int gcol = col0 + wn * 64 + ni * 8 + c * 2;
        float2 bb = *(const float2*)(bj + gcol);
#pragma unroll
        for (int mi = 0; mi < 2; ++mi) {
            int grow = row0 + wm * 32 + mi * 16 + g;
            float2 v0 = make_float2(acc[mi][ni][0] + bb.x, acc[mi][ni][1] + bb.y);
            float2 v1 = make_float2(acc[mi][ni][2] + bb.x, acc[mi][ni][3] + bb.y);
            *(float2*)(out + (size_t)grow * C_ + gcol)       = v0;
            *(float2*)(out + (size_t)(grow + 8) * C_ + gcol) = v1;
        }
    }
}

// ---------------------------------------------------------------------------
// launch
// ---------------------------------------------------------------------------
extern "C" void kernel_launch(void* const* d_in, const int* in_sizes, int n_in,
                              void* d_out, int out_size)
{
    const float* enc     = (const float*)d_in[0];
    const float* dec     = (const float*)d_in[1];
    const float* w_audio = (const float*)d_in[2];
    const float* b_audio = (const float*)d_in[3];
    const float* w_text  = (const float*)d_in[4];
    const float* b_text  = (const float*)d_in[5];
    const float* w_join  = (const float*)d_in[6];
    const float* b_join  = (const float*)d_in[7];
    float* out = (float*)d_out;

    static int smem_set = 0;
    if (!smem_set) {
        cudaFuncSetAttribute(join_kernel, cudaFuncAttributeMaxDynamicSharedMemorySize,
                             SMEM_TOTAL);
        smem_set = 1;
    }

    prep_kernel<<<NB_PREP, 256>>>(enc, dec, w_audio, b_audio, w_text, b_text, w_join);
    join_kernel<<<dim3(C_ / BN, RTOT_ / BM), THREADS, SMEM_TOTAL>>>(b_join, out);
}

// round 13
// speedup vs baseline: 1.1180x; 1.1180x over previous
#include <cuda_runtime.h>
#include <cuda_fp16.h>
#include <cstdint>
#include <cstddef>

// Problem dims
#define B_ 2
#define M_ 384
#define N_ 96
#define D_ 512
#define J_ 640
#define C_ 1024
#define MN_ (M_*N_)        // 36864
#define RTOT_ (B_*MN_)     // 73728

// Join: persistent-ish block: CTA owns 128 rows x full C. 512 threads, 16 warps (4m x 4n).
#define BM 128
#define BN 256
#define BK 64
#define NCT (C_/BN)        // 8 column tiles
#define NKT (J_/BK)        // 10 k tiles
#define NU  (NCT*NKT)      // 80
#define THREADS 512

// smem layout
#define SM_AOFF  0                  // 128 ints
#define SM_TOFF  512
#define SM_H     1024               // h block: 128 rows x 1280B (640 fp16), swizzled
#define H_BYTES  (BM*1280)          // 163840
#define SM_W     (SM_H + H_BYTES)   // 164864 (128B aligned)
#define W_BYTES  (BN*128)           // 32768 per buffer (256 rows x 128B, SW128)
#define SMEM_TOTAL (SM_W + 2*W_BYTES)  // 230400

// prep grid split (256-thread blocks) — unchanged from R12
#define NB_WPACK (((C_/32)*(J_/32))/2)   // 320
#define NB_ENC   ((B_*M_/16)*(J_/128))   // 240
#define NB_DEC   ((B_*N_/16)*(J_/128))   // 60
#define NB_PREP  (NB_WPACK + NB_ENC + NB_DEC)  // 620

// Scratch (device globals)
__device__ __half g_ah[B_*M_*J_];
__device__ __half g_th[B_*N_*J_];
__device__ __half g_wh[(size_t)C_*J_];   // w_join transposed [col][j], fp16

// ---------------------------------------------------------------------------
// helpers
// ---------------------------------------------------------------------------
__device__ __forceinline__ uint32_t smem_u32(const void* p) {
    uint32_t a;
    asm("{ .reg .u64 t; cvta.to.shared.u64 t, %1; cvt.u32.u64 %0, t; }"
        : "=r"(a) : "l"(p));
    return a;
}
__device__ __forceinline__ float fast_tanh(float x) {
    float r;
    asm("tanh.approx.f32 %0, %1;" : "=f"(r) : "f"(x));
    return r;
}
__device__ __forceinline__ unsigned pack_h2(float lo, float hi) {
    unsigned r;
    asm("cvt.rn.f16x2.f32 %0, %2, %1;" : "=r"(r) : "f"(lo), "f"(hi));
    return r;
}
__device__ __forceinline__ void mma_f16(float d[4],
                                        unsigned a0, unsigned a1, unsigned a2, unsigned a3,
                                        unsigned b0, unsigned b1) {
    asm volatile(
        "mma.sync.aligned.m16n8k16.row.col.f32.f16.f16.f32 "
        "{%0,%1,%2,%3}, {%4,%5,%6,%7}, {%8,%9}, {%0,%1,%2,%3};"
        : "+f"(d[0]), "+f"(d[1]), "+f"(d[2]), "+f"(d[3])
        : "r"(a0), "r"(a1), "r"(a2), "r"(a3), "r"(b0), "r"(b1));
}
__device__ __forceinline__ void ldm_x4(unsigned r[4], uint32_t addr) {
    asm volatile("ldmatrix.sync.aligned.m8n8.x4.shared.b16 {%0,%1,%2,%3}, [%4];"
        : "=r"(r[0]), "=r"(r[1]), "=r"(r[2]), "=r"(r[3]) : "r"(addr));
}
__device__ __forceinline__ void cp_async16(uint32_t dst, const void* src) {
    asm volatile("cp.async.cg.shared.global [%0], [%1], 16;" :: "r"(dst), "l"(src));
}
#define CP_COMMIT() asm volatile("cp.async.commit_group;" ::: "memory")
#define CP_WAIT0()  asm volatile("cp.async.wait_group 0;" ::: "memory")

__device__ __forceinline__ uint4 h_combine(uint4 a, uint4 t) {
    uint4 q;
    unsigned* av = (unsigned*)&a;
    unsigned* tv = (unsigned*)&t;
    unsigned* qv = (unsigned*)&q;
#pragma unroll
    for (int i = 0; i < 4; ++i) {
        float2 af = __half22float2(*(__half2*)&av[i]);
        float2 tf = __half22float2(*(__half2*)&tv[i]);
        qv[i] = pack_h2(fast_tanh(af.x + tf.x), fast_tanh(af.y + tf.y));
    }
    return q;
}

// ---------------------------------------------------------------------------
// Fused prep kernel (unchanged from R12), 256 threads/block
// ---------------------------------------------------------------------------
__device__ __forceinline__ void proj_part(
    const float* __restrict__ x, const float* __restrict__ w,
    const float* __restrict__ bias, __half* __restrict__ outp,
    int rb, int cb, int tid)
{
    __shared__ float xs[16][D_];
    const int r0 = rb * 16;
    const int j  = cb * 128 + (tid & 31) * 4;
    const int rw = tid >> 5;

    for (int i = tid; i < 16 * D_ / 4; i += 256)
        ((float4*)xs)[i] = ((const float4*)x)[(size_t)r0 * (D_ / 4) + i];
    __syncthreads();

    float4 a0 = make_float4(0.f, 0.f, 0.f, 0.f);
    float4 a1 = make_float4(0.f, 0.f, 0.f, 0.f);
#pragma unroll 8
    for (int k = 0; k < D_; ++k) {
        float4 wv = *(const float4*)&w[(size_t)k * J_ + j];
        float x0 = xs[rw][k], x1 = xs[rw + 8][k];
        a0.x += x0 * wv.x; a0.y += x0 * wv.y; a0.z += x0 * wv.z; a0.w += x0 * wv.w;
        a1.x += x1 * wv.x; a1.y += x1 * wv.y; a1.z += x1 * wv.z; a1.w += x1 * wv.w;
    }
    float4 bb = *(const float4*)&bias[j];
    uint2 o0, o1;
    o0.x = pack_h2(a0.x + bb.x, a0.y + bb.y);
    o0.y = pack_h2(a0.z + bb.z, a0.w + bb.w);
    o1.x = pack_h2(a1.x + bb.x, a1.y + bb.y);
    o1.y = pack_h2(a1.z + bb.z, a1.w + bb.w);
    *(uint2*)&outp[(size_t)(r0 + rw) * J_ + j]     = o0;
    *(uint2*)&outp[(size_t)(r0 + rw + 8) * J_ + j] = o1;
}

__global__ __launch_bounds__(256) void prep_kernel(
    const float* __restrict__ enc, const float* __restrict__ dec,
    const float* __restrict__ w_audio, const float* __restrict__ b_audio,
    const float* __restrict__ w_text,  const float* __restrict__ b_text,
    const float* __restrict__ wj)
{
    const int bid = blockIdx.x;
    const int tid = threadIdx.x;

    if (bid < NB_WPACK) {
        __shared__ float t[2][32][33];
        const int tt  = tid >> 7;
        const int lt  = tid & 127;
        const int tile = bid * 2 + tt;
        const int c0 = (tile & 31) * 32;
        const int j0 = (tile >> 5) * 32;
        const int tx = lt & 31, ty = lt >> 5;
#pragma unroll
        for (int i = 0; i < 8; ++i)
            t[tt][ty + i * 4][tx] = wj[(size_t)(j0 + ty + i * 4) * C_ + c0 + tx];
        __syncthreads();
#pragma unroll
        for (int i = 0; i < 8; ++i)
            g_wh[(size_t)(c0 + ty + i * 4) * J_ + j0 + tx] =
                __float2half(t[tt][tx][ty + i * 4]);
    } else if (bid < NB_WPACK + NB_ENC) {
        const int pb = bid - NB_WPACK;
        proj_part(enc, w_audio, b_audio, g_ah, pb / 5, pb % 5, tid);
    } else {
        const int pb = bid - NB_WPACK - NB_ENC;
        proj_part(dec, w_text, b_text, g_th, pb / 5, pb % 5, tid);
    }
}

// ---------------------------------------------------------------------------
// Join: h-resident block GEMM. grid = RTOT/128 = 576 CTAs, 512 threads.
// ---------------------------------------------------------------------------
__global__ __launch_bounds__(THREADS, 1) void join_kernel(
    const float* __restrict__ bj, float* __restrict__ out)
{
    extern __shared__ char sm[];
    const uint32_t sb = smem_u32(sm);
    const int tid  = threadIdx.x;
    const int wid  = tid >> 5;
    const int lane = tid & 31;
    const int row0 = blockIdx.x * BM;

    int* aoffS = (int*)(sm + SM_AOFF);
    int* toffS = (int*)(sm + SM_TOFF);
    if (tid < BM) {
        int gr  = row0 + tid;
        int b   = gr / MN_;
        int rem = gr - b * MN_;
        int m   = rem / N_;
        int n   = rem - m * N_;
        aoffS[tid] = (b * M_ + m) * J_;
        toffS[tid] = (b * N_ + n) * J_;
    }
    __syncthreads();

    // ---- issue first w tile (ct=0, kt=0) into buf 0 while h builds ----
    {
        uint32_t wbase = sb + SM_W;
#pragma unroll
        for (int p = 0; p < 4; ++p) {
            int cid = tid + p * THREADS;          // 0..2047
            int n   = cid >> 3;                   // 0..255
            int kk  = cid & 7;
            int kks = kk ^ (n & 7);               // SW128 swizzle
            cp_async16(wbase + n * 128 + kks * 16,
                       g_wh + (size_t)n * J_ + kk * 8);
        }
        CP_COMMIT();
    }

    // ---- build resident h block: 128 rows x 80 chunks (16B), swizzled ----
    // mapping: r = (tid>>3) + (p&1)*64 ; cc = (tid&7) + (p>>1)*8
    // LDG 128B-coalesced per 8 lanes; STS conflict-free under swizzle.
#pragma unroll
    for (int p = 0; p < 20; ++p) {
        int r  = (tid >> 3) + (p & 1) * 64;
        int cc = (tid & 7) + (p >> 1) * 8;
        uint4 av = *(const uint4*)(g_ah + aoffS[r] + cc * 8);
        uint4 tv = *(const uint4*)(g_th + toffS[r] + cc * 8);
        uint32_t off = (uint32_t)r * 1280 +
                       (((cc & ~7) | ((cc ^ r) & 7)) << 4);
        *(uint4*)(sm + SM_H + off) = h_combine(av, tv);
    }
    CP_WAIT0();
    __syncthreads();

    // ---- lane constants ----
    const int wm = wid & 3;               // 4 m-warps of 32 rows
    const int wn = wid >> 2;              // 4 n-warps of 64 cols
    const int g  = lane >> 2;
    const int c  = lane & 3;
    const int l7 = lane & 7;
    const int lm = lane >> 3;
    const int hx   = lm >> 1;             // a: k-half select
    const int bsel = lm & 1;              // b: k-half select

    // a-frag row per lane (mi 0/1), base byte addr in h
    const uint32_t aBase0 = sb + SM_H +
        (uint32_t)(wm * 32 + (lm & 1) * 8 + l7) * 1280;
    const uint32_t aBase1 = aBase0 + 16 * 1280;
    // b-frag row bases (p 0..3) within w buffer
    uint32_t bRow[4];
#pragma unroll
    for (int p = 0; p < 4; ++p)
        bRow[p] = (uint32_t)(wn * 64 + p * 16 + (lm >> 1) * 8 + l7) * 128;

    float acc[2][8][4];
#pragma unroll
    for (int mi = 0; mi < 2; ++mi)
#pragma unroll
        for (int ni = 0; ni < 8; ++ni)
#pragma unroll
            for (int q = 0; q < 4; ++q) acc[mi][ni][q] = 0.f;

    // ---- main sweep: 8 col tiles x 10 k tiles ----
    int ct = 0, kt = 0;
    for (int u = 0; u < NU; ++u) {
        const int cb = u & 1;
        const int nb = cb ^ 1;
        int ktn = kt + 1, ctn = ct;
        if (ktn == NKT) { ktn = 0; ctn = ct + 1; }

        if (u < NU - 1) {
            uint32_t wbase = sb + SM_W + nb * W_BYTES;
            const __half* wsrc = g_wh + (size_t)ctn * BN * J_ + ktn * BK;
#pragma unroll
            for (int p = 0; p < 4; ++p) {
                int cid = tid + p * THREADS;
                int n   = cid >> 3;
                int kk  = cid & 7;
                int kks = kk ^ (n & 7);
                cp_async16(wbase + n * 128 + kks * 16,
                           wsrc + (size_t)n * J_ + kk * 8);
            }
            CP_COMMIT();
        }

        // compute: 4 k-steps of 16 on (h resident, w buf cb)
        const uint32_t ktc = (uint32_t)kt * 128;
        const uint32_t wb  = sb + SM_W + cb * W_BYTES;
#pragma unroll
        for (int ks = 0; ks < 4; ++ks) {
            const uint32_t xa = (uint32_t)((((ks * 2 + hx) ^ l7) & 7) << 4);
            const uint32_t xb = (uint32_t)((((ks * 2 + bsel) ^ l7) & 7) << 4);
            unsigned af[2][4];
            ldm_x4(af[0], aBase0 + ktc + xa);
            ldm_x4(af[1], aBase1 + ktc + xa);
            unsigned bf[4][4];
#pragma unroll
            for (int p = 0; p < 4; ++p)
                ldm_x4(bf[p], wb + bRow[p] + xb);
#pragma unroll
            for (int p = 0; p < 4; ++p)
#pragma unroll
                for (int mi = 0; mi < 2; ++mi) {
                    mma_f16(acc[mi][2 * p],
                            af[mi][0], af[mi][1], af[mi][2], af[mi][3],
                            bf[p][0], bf[p][1]);
                    mma_f16(acc[mi][2 * p + 1],
                            af[mi][0], af[mi][1], af[mi][2], af[mi][3],
                            bf[p][2], bf[p][3]);
                }
        }

        // epilogue at end of each column tile
        if (kt == NKT - 1) {
            const int colE = ct * BN + wn * 64;
#pragma unroll
            for (int ni = 0; ni < 8; ++ni) {
                int gcol = colE + ni * 8 + c * 2;
                float2 bb = *(const float2*)(bj + gcol);
#pragma unroll
                for (int mi = 0; mi < 2; ++mi) {
                    int grow = row0 + wm * 32 + mi * 16 + g;
                    float2 v0 = make_float2(acc[mi][ni][0] + bb.x,
                                            acc[mi][ni][1] + bb.y);
                    float2 v1 = make_float2(acc[mi][ni][2] + bb.x,
                                            acc[mi][ni][3] + bb.y);
                    *(float2*)(out + (size_t)grow * C_ + gcol)       = v0;
                    *(float2*)(out + (size_t)(grow + 8) * C_ + gcol) = v1;
                    acc[mi][ni][0] = 0.f; acc[mi][ni][1] = 0.f;
                    acc[mi][ni][2] = 0.f; acc[mi][ni][3] = 0.f;
                }
            }
        }

        kt = ktn; ct = ctn;
        if (u < NU - 1) {
            CP_WAIT0();
            __syncthreads();
        }
    }
}

// ---------------------------------------------------------------------------
// launch
// ---------------------------------------------------------------------------
extern "C" void kernel_launch(void* const* d_in, const int* in_sizes, int n_in,
                              void* d_out, int out_size)
{
    const float* enc     = (const float*)d_in[0];
    const float* dec     = (const float*)d_in[1];
    const float* w_audio = (const float*)d_in[2];
    const float* b_audio = (const float*)d_in[3];
    const float* w_text  = (const float*)d_in[4];
    const float* b_text  = (const float*)d_in[5];
    const float* w_join  = (const float*)d_in[6];
    const float* b_join  = (const float*)d_in[7];
    float* out = (float*)d_out;

    static int smem_set = 0;
    if (!smem_set) {
        cudaFuncSetAttribute(join_kernel, cudaFuncAttributeMaxDynamicSharedMemorySize,
                             SMEM_TOTAL);
        smem_set = 1;
    }

    prep_kernel<<<NB_PREP, 256>>>(enc, dec, w_audio, b_audio, w_text, b_text, w_join);
    join_kernel<<<RTOT_ / BM, THREADS, SMEM_TOTAL>>>(b_join, out);
}